// round 9
// baseline (speedup 1.0000x reference)
#include <cuda_runtime.h>
#include <cstdint>

#define DIMD 2048
#define NC 12
#define NC2 144
#define ROWS 32
#define NCTA 1024
#define THREADS 256
#define DC 64
#define NCH 32
#define STRA 148   // Ct stride (words): banks 20*gq+tg all-distinct
#define STRB 152   // B stride (words): 152 % 32 == 24 -> uint2 conflict-free
#define EPSV 1e-5f

// ---- smem byte layout (per CTA: 97792 B -> 2 CTAs/SM) ----
#define OFF_CT 0                       // Ct [32][148] tf32 (18944 B)
#define OFF_B0 18944                   // WiT buf0 [64][152w] (38912 B)
#define OFF_B1 57856                   // WiT buf1
#define OFF_LN 96768                   // LN partials [4][32][2] (1024 B)
#define SMEM_BYTES 97792
// phase A staging aliases inside buf1 (bytes)
#define OFF_AX0 57856                  // x fp32 [32][68w] (8704 B)
#define OFF_AX1 66560
#define OFF_AWT0 75264                 // Wt tf32 [32][76w] (9728 B)
#define OFF_AWT1 84992
// phase A reduction aliases (word indices, inside buf1)
#define FOFF_RED (OFF_B1 / 4)          // partials [4][32][32] (4096 w)
#define FOFF_PV (FOFF_RED + 4096)      // pos/vel [32][24] (768 w)

__device__ __align__(16) uint32_t g_WiT[DIMD * NC2];  // [n][perm(k)] tf32
__device__ __align__(16) uint32_t g_WT[32 * DIMD];    // [n][k] tf32 (pos|vel|pad)

__device__ __forceinline__ uint32_t smem_u32(const void* p) {
    uint32_t a;
    asm("{ .reg .u64 t; cvta.to.shared.u64 t, %1; cvt.u32.u64 %0, t; }"
        : "=r"(a) : "l"(p));
    return a;
}
__device__ __forceinline__ uint32_t to_tf32(float x) {
    uint32_t t;
    asm("cvt.rna.tf32.f32 %0, %1;" : "=r"(t) : "f"(x));
    return t;
}
// pair-permute within each k8 block: pos 2j <- k=j, pos 2j+1 <- k=j+4
__device__ __forceinline__ int kperm(int k) {
    return (k & ~7) + 2 * (k & 3) + ((k >> 2) & 1);
}
__device__ __forceinline__ void mma_tf32(float& c0, float& c1, float& c2, float& c3,
                                         uint32_t a0, uint32_t a1, uint32_t a2,
                                         uint32_t a3, uint32_t b0, uint32_t b1) {
    asm volatile(
        "mma.sync.aligned.m16n8k8.row.col.f32.tf32.tf32.f32 "
        "{%0,%1,%2,%3},{%4,%5,%6,%7},{%8,%9},{%0,%1,%2,%3};"
        : "+f"(c0), "+f"(c1), "+f"(c2), "+f"(c3)
        : "r"(a0), "r"(a1), "r"(a2), "r"(a3), "r"(b0), "r"(b1));
}
__device__ __forceinline__ void cpa16(uint32_t dst, const void* src) {
    asm volatile("cp.async.ca.shared.global [%0], [%1], 16;"
                 :: "r"(dst), "l"(src) : "memory");
}

// ---- pre-kernels ----
__global__ void wit_kernel(const float* __restrict__ Wi) {
    int idx = blockIdx.x * 256 + threadIdx.x;  // 144*2048
    int k = idx >> 11;
    int n = idx & 2047;
    g_WiT[n * NC2 + kperm(k)] = to_tf32(Wi[idx]);
}
__global__ void wt_kernel(const float* __restrict__ Wp, const float* __restrict__ Wv) {
    int idx = blockIdx.x * 256 + threadIdx.x;  // 32*2048
    int n = idx >> 11;
    int k = idx & 2047;
    float v = 0.f;
    if (n < NC) v = Wp[k * NC + n];
    else if (n < 2 * NC) v = Wv[k * NC + n - NC];
    g_WT[idx] = to_tf32(v);
}

__global__ __launch_bounds__(THREADS, 2)
void gil_kernel(const float* __restrict__ x, const float* __restrict__ Wp,
                const float* __restrict__ bp, const float* __restrict__ Wv,
                const float* __restrict__ bv, const float* __restrict__ Wi,
                const float* __restrict__ bi, const float* __restrict__ gamma,
                const float* __restrict__ beta, float* __restrict__ out) {
    extern __shared__ char smc[];
    float* smf = (float*)smc;
    uint32_t* smu = (uint32_t*)smc;
    const int tid = threadIdx.x;
    const int w = tid >> 5, lane = tid & 31;
    const int gq = lane >> 2, tg = lane & 3;
    const int rowbase = blockIdx.x * ROWS;
    const uint32_t smem_base = smem_u32(smc);

    // -------- prefetch WiT chunk 0 into buf0 (overlaps phase A) -------------
    {
        const char* src = (const char*)g_WiT;  // chunk 0 = n 0..63
#pragma unroll
        for (int j = 0; j < 9; j++) {
            int e = (tid + THREADS * j) * 16;  // < 36864
            int n = e / 576;
            int ko = e - n * 576;
            cpa16(smem_base + OFF_B0 + n * 608 + ko, src + e);
        }
        asm volatile("cp.async.commit_group;" ::: "memory");
    }
    // -------- phase A stage kc=0 --------------------------------------------
    {
#pragma unroll
        for (int j = 0; j < 2; j++) {
            int gi = tid + THREADS * j;  // < 512
            int r = gi >> 4, kq = gi & 15;
            cpa16(smem_base + OFF_AX0 + r * 272 + kq * 16,
                  x + (rowbase + r) * DIMD + kq * 4);
        }
#pragma unroll
        for (int j = 0; j < 2; j++) {
            int gi = tid + THREADS * j;  // < 512
            int n = gi >> 4, kq = gi & 15;
            cpa16(smem_base + OFF_AWT0 + n * 304 + kq * 16,
                  g_WT + n * DIMD + kq * 4);
        }
        asm volatile("cp.async.commit_group;" ::: "memory");
    }

    // ====== Phase A (tensor): pos/vel = x @ [Wp|Wv], K split 4-way ==========
    const int ks = w & 3;   // k16-slice within each 64-k stage
    const int nh = w >> 2;  // n-half (16 cols)
    float pa[2][2][4];
#pragma unroll
    for (int m = 0; m < 2; m++)
#pragma unroll
        for (int j = 0; j < 2; j++)
#pragma unroll
            for (int q = 0; q < 4; q++) pa[m][j][q] = 0.f;

    for (int kc = 0; kc < DIMD / 64; kc++) {
        if (kc < DIMD / 64 - 1) {  // stage kc+1 into alternate buffers
            int kn = kc + 1;
            uint32_t axd = ((kn & 1) ? OFF_AX1 : OFF_AX0);
            uint32_t awd = ((kn & 1) ? OFF_AWT1 : OFF_AWT0);
#pragma unroll
            for (int j = 0; j < 2; j++) {
                int gi = tid + THREADS * j;
                int r = gi >> 4, kq = gi & 15;
                cpa16(smem_base + axd + r * 272 + kq * 16,
                      x + (rowbase + r) * DIMD + kn * 64 + kq * 4);
            }
#pragma unroll
            for (int j = 0; j < 2; j++) {
                int gi = tid + THREADS * j;
                int n = gi >> 4, kq = gi & 15;
                cpa16(smem_base + awd + n * 304 + kq * 16,
                      g_WT + n * DIMD + kn * 64 + kq * 4);
            }
            asm volatile("cp.async.commit_group;" ::: "memory");
            asm volatile("cp.async.wait_group 1;" ::: "memory");
        } else {
            asm volatile("cp.async.wait_group 0;" ::: "memory");
        }
        __syncthreads();  // stage kc copies from ALL threads visible

        const float* X = (const float*)(smc + ((kc & 1) ? OFF_AX1 : OFF_AX0));
        const uint32_t* WT = (const uint32_t*)(smc + ((kc & 1) ? OFF_AWT1 : OFF_AWT0));
        uint32_t wb[2][2][2];  // [k8i][ntile][lo/hi]
#pragma unroll
        for (int k8i = 0; k8i < 2; k8i++) {
            int kb = ks * 16 + k8i * 8 + tg;
            wb[k8i][0][0] = WT[(nh * 16 + gq) * 76 + kb];
            wb[k8i][0][1] = WT[(nh * 16 + gq) * 76 + kb + 4];
            wb[k8i][1][0] = WT[(nh * 16 + 8 + gq) * 76 + kb];
            wb[k8i][1][1] = WT[(nh * 16 + 8 + gq) * 76 + kb + 4];
        }
#pragma unroll
        for (int m = 0; m < 2; m++) {
#pragma unroll
            for (int k8i = 0; k8i < 2; k8i++) {
                const float* Xr = X + (m * 16 + gq) * 68 + ks * 16 + k8i * 8 + tg;
                uint32_t a0 = to_tf32(Xr[0]);
                uint32_t a2 = to_tf32(Xr[4]);
                uint32_t a1 = to_tf32(Xr[8 * 68]);
                uint32_t a3 = to_tf32(Xr[8 * 68 + 4]);
                mma_tf32(pa[m][0][0], pa[m][0][1], pa[m][0][2], pa[m][0][3],
                         a0, a1, a2, a3, wb[k8i][0][0], wb[k8i][0][1]);
                mma_tf32(pa[m][1][0], pa[m][1][1], pa[m][1][2], pa[m][1][3],
                         a0, a1, a2, a3, wb[k8i][1][0], wb[k8i][1][1]);
            }
        }
        __syncthreads();  // all warps done with this stage buffer
    }
    // write per-slice partials (RED aliases staging; consumption done)
#pragma unroll
    for (int m = 0; m < 2; m++) {
#pragma unroll
        for (int j = 0; j < 2; j++) {
            int n = nh * 16 + j * 8 + 2 * tg;
            float* dst = smf + FOFF_RED + ks * 1024 + (m * 16 + gq) * 32 + n;
            *(float2*)dst = make_float2(pa[m][j][0], pa[m][j][1]);
            *(float2*)(dst + 8 * 32) = make_float2(pa[m][j][2], pa[m][j][3]);
        }
    }
    __syncthreads();
    // reduce 4 k-slices + bias -> sPV [32][24]
#pragma unroll
    for (int q = 0; q < 3; q++) {
        int o = tid + THREADS * q;  // < 768
        int row = o / 24, c = o - row * 24;
        float v = 0.f;
#pragma unroll
        for (int s = 0; s < 4; s++) v += smf[FOFF_RED + s * 1024 + row * 32 + c];
        v += (c < NC) ? bp[c] : bv[c - NC];
        smf[FOFF_PV + row * 24 + c] = v;
    }
    __syncthreads();

    // ============ Phase B: sCt[row][k] natural layout =======================
#pragma unroll
    for (int q = 0; q < 18; q++) {
        int t = tid + THREADS * q;  // < 4608
        int row = t / NC2;
        int k = t - row * NC2;
        int i = k / NC, j = k - i * NC;
        float ct = smf[FOFF_PV + row * 24 + i] * smf[FOFF_PV + row * 24 + NC + j];
        smu[row * STRA + k] = to_tf32(ct);
    }
    __syncthreads();  // Ct visible; PV dead after this point

    // ===== Hoist A-fragments for this warp's 16 rows (reused all chunks) ====
    const int rg = w & 1;   // rowgroup (16 rows)
    const int cg = w >> 1;  // colgroup (16 cols of each 64-chunk)
    const int rowA = rowbase + rg * 16 + gq;
    const int rowB = rowA + 8;
    uint32_t af[18][4];
    {
        const uint32_t* A0 = smu + (rg * 16 + gq) * STRA + tg;
        const uint32_t* A1 = A0 + 8 * STRA;
#pragma unroll
        for (int k8 = 0; k8 < 18; k8++) {
            af[k8][0] = A0[k8 * 8];
            af[k8][1] = A1[k8 * 8];
            af[k8][2] = A0[k8 * 8 + 4];
            af[k8][3] = A1[k8 * 8 + 4];
        }
    }

    // ================= Phase C: chunk loop ==================================
    float lsA = 0.f, qA = 0.f, lsB = 0.f, qB = 0.f;

    for (int c = 0; c < NCH; c++) {
        if (c < NCH - 1) {
            const char* src = (const char*)g_WiT + (c + 1) * DC * NC2 * 4;
            uint32_t bufoff = ((c + 1) & 1) ? OFF_B1 : OFF_B0;
#pragma unroll
            for (int j = 0; j < 9; j++) {
                int e = (tid + THREADS * j) * 16;
                int n = e / 576;
                int ko = e - n * 576;
                cpa16(smem_base + bufoff + n * 608 + ko, src + e);
            }
            asm volatile("cp.async.commit_group;" ::: "memory");
            asm volatile("cp.async.wait_group 1;" ::: "memory");
        } else {
            asm volatile("cp.async.wait_group 0;" ::: "memory");
        }
        __syncthreads();  // chunk c copies from ALL threads visible

        const uint32_t* Bb = smu + ((c & 1) ? OFF_B1 : OFF_B0) / 4 +
                             (cg * 16 + gq) * STRB + 2 * tg;
        float acc[2][4];
#pragma unroll
        for (int nt = 0; nt < 2; nt++)
#pragma unroll
            for (int q = 0; q < 4; q++) acc[nt][q] = 0.f;

#pragma unroll
        for (int k8 = 0; k8 < 18; k8++) {
            uint2 b0 = *(const uint2*)(Bb + 0 * 8 * STRB + k8 * 8);
            uint2 b1 = *(const uint2*)(Bb + 1 * 8 * STRB + k8 * 8);
            mma_tf32(acc[0][0], acc[0][1], acc[0][2], acc[0][3],
                     af[k8][0], af[k8][1], af[k8][2], af[k8][3], b0.x, b0.y);
            mma_tf32(acc[1][0], acc[1][1], acc[1][2], acc[1][3],
                     af[k8][0], af[k8][1], af[k8][2], af[k8][3], b1.x, b1.y);
        }

        // epilogue: y = inter + x + bi ; store ; LN partials
        int cbase = c * DC + cg * 16;
#pragma unroll
        for (int nt = 0; nt < 2; nt++) {
            int col = cbase + nt * 8 + 2 * tg;
            float2 biv = *(const float2*)(bi + col);
            float2 xa = *(const float2*)(x + rowA * DIMD + col);
            float y0 = acc[nt][0] + xa.x + biv.x;
            float y1 = acc[nt][1] + xa.y + biv.y;
            *(float2*)(out + rowA * DIMD + col) = make_float2(y0, y1);
            lsA += y0 + y1;
            qA += y0 * y0 + y1 * y1;
            float2 xb = *(const float2*)(x + rowB * DIMD + col);
            float y2 = acc[nt][2] + xb.x + biv.x;
            float y3 = acc[nt][3] + xb.y + biv.y;
            *(float2*)(out + rowB * DIMD + col) = make_float2(y2, y3);
            lsB += y2 + y3;
            qB += y2 * y2 + y3 * y3;
        }
        __syncthreads();  // done reading buf[c&1] before next prefetch
    }

    // ================= LN stats =============================================
#pragma unroll
    for (int off = 1; off <= 2; off <<= 1) {
        lsA += __shfl_xor_sync(0xffffffffu, lsA, off);
        qA += __shfl_xor_sync(0xffffffffu, qA, off);
        lsB += __shfl_xor_sync(0xffffffffu, lsB, off);
        qB += __shfl_xor_sync(0xffffffffu, qB, off);
    }
    float* sLN = (float*)(smc + OFF_LN);
    if (tg == 0) {
        int rA = rg * 16 + gq, rB = rA + 8;
        *(float2*)(sLN + (cg * 32 + rA) * 2) = make_float2(lsA, qA);
        *(float2*)(sLN + (cg * 32 + rB) * 2) = make_float2(lsB, qB);
    }
    __syncthreads();
    float sumA = 0.f, ssqA = 0.f, sumB = 0.f, ssqB = 0.f;
#pragma unroll
    for (int g2 = 0; g2 < 4; g2++) {
        float2 va = *(const float2*)(sLN + (g2 * 32 + rg * 16 + gq) * 2);
        float2 vb = *(const float2*)(sLN + (g2 * 32 + rg * 16 + gq + 8) * 2);
        sumA += va.x; ssqA += va.y;
        sumB += vb.x; ssqB += vb.y;
    }
    float muA = sumA * (1.0f / DIMD);
    float rsA = rsqrtf(ssqA * (1.0f / DIMD) - muA * muA + EPSV);
    float muB = sumB * (1.0f / DIMD);
    float rsB = rsqrtf(ssqB * (1.0f / DIMD) - muB * muB + EPSV);

    // ================= Phase D: normalize own writes ========================
    for (int c = 0; c < NCH; c++) {
#pragma unroll
        for (int nt = 0; nt < 2; nt++) {
            int col = c * DC + cg * 16 + nt * 8 + 2 * tg;
            float2 g2 = *(const float2*)(gamma + col);
            float2 b2 = *(const float2*)(beta + col);
            float2 ya = *(const float2*)(out + rowA * DIMD + col);
            ya.x = (ya.x - muA) * rsA * g2.x + b2.x;
            ya.y = (ya.y - muA) * rsA * g2.y + b2.y;
            *(float2*)(out + rowA * DIMD + col) = ya;
            float2 yb = *(const float2*)(out + rowB * DIMD + col);
            yb.x = (yb.x - muB) * rsB * g2.x + b2.x;
            yb.y = (yb.y - muB) * rsB * g2.y + b2.y;
            *(float2*)(out + rowB * DIMD + col) = yb;
        }
    }
}

extern "C" void kernel_launch(void* const* d_in, const int* in_sizes, int n_in,
                              void* d_out, int out_size) {
    const float* x     = (const float*)d_in[0];
    const float* Wp    = (const float*)d_in[1];
    const float* bp    = (const float*)d_in[2];
    const float* Wv    = (const float*)d_in[3];
    const float* bv    = (const float*)d_in[4];
    const float* Wi    = (const float*)d_in[5];
    const float* bi    = (const float*)d_in[6];
    const float* gamma = (const float*)d_in[7];
    const float* beta  = (const float*)d_in[8];
    float* out = (float*)d_out;

    wit_kernel<<<(DIMD * NC2) / 256, 256>>>(Wi);
    wt_kernel<<<(32 * DIMD) / 256, 256>>>(Wp, Wv);
    cudaFuncSetAttribute(gil_kernel, cudaFuncAttributeMaxDynamicSharedMemorySize,
                         SMEM_BYTES);
    gil_kernel<<<NCTA, THREADS, SMEM_BYTES>>>(x, Wp, bp, Wv, bv, Wi, bi, gamma,
                                              beta, out);
}

// round 10
// speedup vs baseline: 1.7247x; 1.7247x over previous
#include <cuda_runtime.h>
#include <cstdint>

#define DIMD 2048
#define NC 12
#define NC2 144
#define ROWS 64
#define NCTA 512
#define THREADS 512
#define DC 128
#define NCH 16
#define STRA 148   // Ct stride (words): banks 20*gq+tg all-distinct
#define STRB 168   // B stride (words): 168 % 32 == 8 -> uint2 conflict-free
#define EPSV 1e-5f

// ---- smem byte layout ----
#define OFF_CT 0                       // Ct [64][148] tf32 (37888 B)
#define OFF_B0 37888                   // WiT buf0 [128][168w] (86016 B)
#define OFF_B1 123904                  // WiT buf1 (86016 B)
#define OFF_PV 209920                  // pos/vel [64][24]w dedicated (6144 B)
#define OFF_LN 216064                  // LN partials (2048 B)
#define SMEM_BYTES 218112
// phase A staging aliases (bytes) inside B0/B1 (dead during phase A)
#define OFF_AX0 37888                  // x fp32 [64][132w] (33792 B)
#define OFF_AX1 71680
#define OFF_AWT0 105472                // Wt tf32 [32][140w] (17920 B)
#define OFF_AWT1 123392                // (tail reaches 141312, inside B1: safe)
// phase A reduction alias (word indices; aliases AX bufs, dead by then)
#define FOFF_RED (OFF_B0 / 4)          // partials [8][64][32] (16384 w)
#define FOFF_PV (OFF_PV / 4)

__device__ __align__(16) uint32_t g_WiT[DIMD * NC2];  // [n][perm(k)] tf32
__device__ __align__(16) uint32_t g_WT[32 * DIMD];    // [n][k] tf32 (pos|vel|pad)

__device__ __forceinline__ uint32_t smem_u32(const void* p) {
    uint32_t a;
    asm("{ .reg .u64 t; cvta.to.shared.u64 t, %1; cvt.u32.u64 %0, t; }"
        : "=r"(a) : "l"(p));
    return a;
}
__device__ __forceinline__ uint32_t to_tf32(float x) {
    uint32_t t;
    asm("cvt.rna.tf32.f32 %0, %1;" : "=r"(t) : "f"(x));
    return t;
}
// pair-permute within each k8 block: pos 2j <- k=j, pos 2j+1 <- k=j+4
__device__ __forceinline__ int kperm(int k) {
    return (k & ~7) + 2 * (k & 3) + ((k >> 2) & 1);
}
__device__ __forceinline__ void mma_tf32(float& c0, float& c1, float& c2, float& c3,
                                         uint32_t a0, uint32_t a1, uint32_t a2,
                                         uint32_t a3, uint32_t b0, uint32_t b1) {
    asm volatile(
        "mma.sync.aligned.m16n8k8.row.col.f32.tf32.tf32.f32 "
        "{%0,%1,%2,%3},{%4,%5,%6,%7},{%8,%9},{%0,%1,%2,%3};"
        : "+f"(c0), "+f"(c1), "+f"(c2), "+f"(c3)
        : "r"(a0), "r"(a1), "r"(a2), "r"(a3), "r"(b0), "r"(b1));
}
__device__ __forceinline__ void cpa16(uint32_t dst, const void* src) {
    asm volatile("cp.async.ca.shared.global [%0], [%1], 16;"
                 :: "r"(dst), "l"(src) : "memory");
}

// ---- pre-kernels ----
__global__ void wit_kernel(const float* __restrict__ Wi) {
    int idx = blockIdx.x * 256 + threadIdx.x;  // 144*2048
    int k = idx >> 11;
    int n = idx & 2047;
    g_WiT[n * NC2 + kperm(k)] = to_tf32(Wi[idx]);
}
__global__ void wt_kernel(const float* __restrict__ Wp, const float* __restrict__ Wv) {
    int idx = blockIdx.x * 256 + threadIdx.x;  // 32*2048
    int n = idx >> 11;
    int k = idx & 2047;
    float v = 0.f;
    if (n < NC) v = Wp[k * NC + n];
    else if (n < 2 * NC) v = Wv[k * NC + n - NC];
    g_WT[idx] = to_tf32(v);
}

__global__ __launch_bounds__(THREADS, 1)
void gil_kernel(const float* __restrict__ x, const float* __restrict__ Wp,
                const float* __restrict__ bp, const float* __restrict__ Wv,
                const float* __restrict__ bv, const float* __restrict__ Wi,
                const float* __restrict__ bi, const float* __restrict__ gamma,
                const float* __restrict__ beta, float* __restrict__ out) {
    extern __shared__ char smc[];
    float* smf = (float*)smc;
    uint32_t* smu = (uint32_t*)smc;
    const int tid = threadIdx.x;
    const int w = tid >> 5, lane = tid & 31;
    const int gq = lane >> 2, tg = lane & 3;
    const int rowbase = blockIdx.x * ROWS;
    const uint32_t smem_base = smem_u32(smc);

    // -------- prologue: phase A stage 0 (X + WT, KC=128) --------------------
    {
#pragma unroll
        for (int j = 0; j < 4; j++) {
            int gi = tid + THREADS * j;  // < 2048
            int r = gi >> 5, kq = gi & 31;
            cpa16(smem_base + OFF_AX0 + r * 528 + kq * 16,
                  x + (rowbase + r) * DIMD + kq * 4);
        }
#pragma unroll
        for (int j = 0; j < 2; j++) {
            int gi = tid + THREADS * j;  // < 1024
            int n = gi >> 5, kq = gi & 31;
            cpa16(smem_base + OFF_AWT0 + n * 560 + kq * 16,
                  g_WT + n * DIMD + kq * 4);
        }
        asm volatile("cp.async.commit_group;" ::: "memory");
    }

    // ====== Phase A (tensor): pos/vel = x @ [Wp|Wv], 16 stages of KC=128 ====
    const int k8w = w & 7;   // k16-slice within each 128-k stage
    const int nh = w >> 3;   // n-half
    float pa[8][4];
#pragma unroll
    for (int i = 0; i < 8; i++)
#pragma unroll
        for (int q = 0; q < 4; q++) pa[i][q] = 0.f;

    for (int kc = 0; kc < DIMD / 128; kc++) {
        if (kc < DIMD / 128 - 1) {  // stage kc+1 into alternate buffers
            int kn = kc + 1;
            uint32_t axd = ((kn & 1) ? OFF_AX1 : OFF_AX0);
            uint32_t awd = ((kn & 1) ? OFF_AWT1 : OFF_AWT0);
#pragma unroll
            for (int j = 0; j < 4; j++) {
                int gi = tid + THREADS * j;
                int r = gi >> 5, kq = gi & 31;
                cpa16(smem_base + axd + r * 528 + kq * 16,
                      x + (rowbase + r) * DIMD + kn * 128 + kq * 4);
            }
#pragma unroll
            for (int j = 0; j < 2; j++) {
                int gi = tid + THREADS * j;
                int n = gi >> 5, kq = gi & 31;
                cpa16(smem_base + awd + n * 560 + kq * 16,
                      g_WT + n * DIMD + kn * 128 + kq * 4);
            }
            asm volatile("cp.async.commit_group;" ::: "memory");
            asm volatile("cp.async.wait_group 1;" ::: "memory");
        } else {
            asm volatile("cp.async.wait_group 0;" ::: "memory");
        }
        __syncthreads();  // stage kc copies from ALL threads visible

        const float* X = (const float*)(smc + ((kc & 1) ? OFF_AX1 : OFF_AX0));
        const uint32_t* WT = (const uint32_t*)(smc + ((kc & 1) ? OFF_AWT1 : OFF_AWT0));
        uint32_t wb[2][2][2];  // [k8i][ntile][lo/hi]
#pragma unroll
        for (int k8i = 0; k8i < 2; k8i++) {
            int kb = k8w * 16 + k8i * 8 + tg;
            wb[k8i][0][0] = WT[(nh * 16 + gq) * 140 + kb];
            wb[k8i][0][1] = WT[(nh * 16 + gq) * 140 + kb + 4];
            wb[k8i][1][0] = WT[(nh * 16 + 8 + gq) * 140 + kb];
            wb[k8i][1][1] = WT[(nh * 16 + 8 + gq) * 140 + kb + 4];
        }
#pragma unroll
        for (int m = 0; m < 4; m++) {
#pragma unroll
            for (int k8i = 0; k8i < 2; k8i++) {
                const float* Xr = X + (m * 16 + gq) * 132 + k8w * 16 + k8i * 8 + tg;
                uint32_t a0 = to_tf32(Xr[0]);
                uint32_t a2 = to_tf32(Xr[4]);
                uint32_t a1 = to_tf32(Xr[8 * 132]);
                uint32_t a3 = to_tf32(Xr[8 * 132 + 4]);
                mma_tf32(pa[2 * m][0], pa[2 * m][1], pa[2 * m][2], pa[2 * m][3],
                         a0, a1, a2, a3, wb[k8i][0][0], wb[k8i][0][1]);
                mma_tf32(pa[2 * m + 1][0], pa[2 * m + 1][1], pa[2 * m + 1][2],
                         pa[2 * m + 1][3], a0, a1, a2, a3,
                         wb[k8i][1][0], wb[k8i][1][1]);
            }
        }
        __syncthreads();  // all warps done with this stage buffer
    }
    // write per-slice partials (RED aliases AX staging; consumption done)
#pragma unroll
    for (int m = 0; m < 4; m++) {
#pragma unroll
        for (int j = 0; j < 2; j++) {
            int n = (2 * nh + j) * 8 + 2 * tg;
            float* dst = smf + FOFF_RED + k8w * 2048 + (m * 16 + gq) * 32 + n;
            *(float2*)dst = make_float2(pa[2 * m + j][0], pa[2 * m + j][1]);
            *(float2*)(dst + 8 * 32) = make_float2(pa[2 * m + j][2], pa[2 * m + j][3]);
        }
    }
    __syncthreads();
    // reduce 8 k-slices + bias -> sPV (dedicated region)
#pragma unroll
    for (int q = 0; q < 3; q++) {
        int o = tid + THREADS * q;  // < 1536
        int row = o / 24, c = o - row * 24;
        float v = 0.f;
#pragma unroll
        for (int s = 0; s < 8; s++) v += smf[FOFF_RED + s * 2048 + row * 32 + c];
        v += (c < NC) ? bp[c] : bv[c - NC];
        smf[FOFF_PV + row * 24 + c] = v;
    }
    __syncthreads();  // PV ready; RED/staging (B0 region) now dead

    // -------- issue Wi chunk-0 prefetch (hides behind phase B) --------------
    {
        const char* src = (const char*)g_WiT;
#pragma unroll
        for (int j = 0; j < 9; j++) {
            int e = (tid + THREADS * j) * 16;
            int n = e / 576;
            int ko = e - n * 576;
            cpa16(smem_base + OFF_B0 + n * 672 + ko, src + e);
        }
        asm volatile("cp.async.commit_group;" ::: "memory");
    }

    // ============ Phase B: sCt[row][k] natural layout =======================
#pragma unroll
    for (int q = 0; q < 18; q++) {
        int t = tid + THREADS * q;  // < 9216
        int row = t / NC2;
        int k = t - row * NC2;
        int i = k / NC, j = k - i * NC;
        float ct = smf[FOFF_PV + row * 24 + i] * smf[FOFF_PV + row * 24 + NC + j];
        smu[row * STRA + k] = to_tf32(ct);
    }
    __syncthreads();  // Ct visible to all warps

    // ===== Hoist A-fragments for this warp's 16 rows (reused all chunks) ====
    const int r16 = (w & 3) * 16;
    const int cg = w >> 2;
    const int rowA = rowbase + r16 + gq;
    const int rowB = rowA + 8;
    uint32_t af[18][4];
    {
        const uint32_t* A0 = smu + (r16 + gq) * STRA + tg;
        const uint32_t* A1 = A0 + 8 * STRA;
#pragma unroll
        for (int k8 = 0; k8 < 18; k8++) {
            af[k8][0] = A0[k8 * 8];
            af[k8][1] = A1[k8 * 8];
            af[k8][2] = A0[k8 * 8 + 4];
            af[k8][3] = A1[k8 * 8 + 4];
        }
    }

    // ================= Phase C: chunk loop ==================================
    float lsA = 0.f, qA = 0.f, lsB = 0.f, qB = 0.f;

    for (int c = 0; c < NCH; c++) {
        if (c < NCH - 1) {
            const char* src = (const char*)g_WiT + (c + 1) * DC * NC2 * 4;
            uint32_t bufoff = ((c + 1) & 1) ? OFF_B1 : OFF_B0;
#pragma unroll
            for (int j = 0; j < 9; j++) {
                int e = (tid + THREADS * j) * 16;
                int n = e / 576;
                int ko = e - n * 576;
                cpa16(smem_base + bufoff + n * 672 + ko, src + e);
            }
            asm volatile("cp.async.commit_group;" ::: "memory");
            asm volatile("cp.async.wait_group 1;" ::: "memory");
        } else {
            asm volatile("cp.async.wait_group 0;" ::: "memory");
        }
        __syncthreads();  // chunk c copies from ALL threads visible

        // prefetch this chunk's x rows into registers (hidden by MMA loop)
        int cbase = c * DC + cg * 32;
        float2 xpa[4], xpb[4];
#pragma unroll
        for (int nt = 0; nt < 4; nt++) {
            int col = cbase + nt * 8 + 2 * tg;
            xpa[nt] = *(const float2*)(x + rowA * DIMD + col);
            xpb[nt] = *(const float2*)(x + rowB * DIMD + col);
        }

        const uint32_t* Bb = smu + ((c & 1) ? OFF_B1 : OFF_B0) / 4 +
                             (cg * 32 + gq) * STRB + 2 * tg;
        float acc[4][4];
#pragma unroll
        for (int nt = 0; nt < 4; nt++)
#pragma unroll
            for (int q = 0; q < 4; q++) acc[nt][q] = 0.f;

#pragma unroll
        for (int k8 = 0; k8 < 18; k8++) {
            uint2 b0 = *(const uint2*)(Bb + 0 * 8 * STRB + k8 * 8);
            uint2 b1 = *(const uint2*)(Bb + 1 * 8 * STRB + k8 * 8);
            uint2 b2 = *(const uint2*)(Bb + 2 * 8 * STRB + k8 * 8);
            uint2 b3 = *(const uint2*)(Bb + 3 * 8 * STRB + k8 * 8);
            mma_tf32(acc[0][0], acc[0][1], acc[0][2], acc[0][3],
                     af[k8][0], af[k8][1], af[k8][2], af[k8][3], b0.x, b0.y);
            mma_tf32(acc[1][0], acc[1][1], acc[1][2], acc[1][3],
                     af[k8][0], af[k8][1], af[k8][2], af[k8][3], b1.x, b1.y);
            mma_tf32(acc[2][0], acc[2][1], acc[2][2], acc[2][3],
                     af[k8][0], af[k8][1], af[k8][2], af[k8][3], b2.x, b2.y);
            mma_tf32(acc[3][0], acc[3][1], acc[3][2], acc[3][3],
                     af[k8][0], af[k8][1], af[k8][2], af[k8][3], b3.x, b3.y);
        }

        // epilogue: y = inter + x + bi ; store ; LN partials
#pragma unroll
        for (int nt = 0; nt < 4; nt++) {
            int col = cbase + nt * 8 + 2 * tg;
            float2 biv = *(const float2*)(bi + col);
            float y0 = acc[nt][0] + xpa[nt].x + biv.x;
            float y1 = acc[nt][1] + xpa[nt].y + biv.y;
            *(float2*)(out + rowA * DIMD + col) = make_float2(y0, y1);
            lsA += y0 + y1;
            qA += y0 * y0 + y1 * y1;
            float y2 = acc[nt][2] + xpb[nt].x + biv.x;
            float y3 = acc[nt][3] + xpb[nt].y + biv.y;
            *(float2*)(out + rowB * DIMD + col) = make_float2(y2, y3);
            lsB += y2 + y3;
            qB += y2 * y2 + y3 * y3;
        }
        __syncthreads();  // done reading buf[c&1] before next prefetch
    }

    // ================= LN stats =============================================
#pragma unroll
    for (int off = 1; off <= 2; off <<= 1) {
        lsA += __shfl_xor_sync(0xffffffffu, lsA, off);
        qA += __shfl_xor_sync(0xffffffffu, qA, off);
        lsB += __shfl_xor_sync(0xffffffffu, lsB, off);
        qB += __shfl_xor_sync(0xffffffffu, qB, off);
    }
    float* sLN = (float*)(smc + OFF_LN);
    if (tg == 0) {
        int rA = r16 + gq, rB = rA + 8;
        *(float2*)(sLN + (cg * 64 + rA) * 2) = make_float2(lsA, qA);
        *(float2*)(sLN + (cg * 64 + rB) * 2) = make_float2(lsB, qB);
    }
    __syncthreads();
    float sumA = 0.f, ssqA = 0.f, sumB = 0.f, ssqB = 0.f;
#pragma unroll
    for (int g2 = 0; g2 < 4; g2++) {
        float2 va = *(const float2*)(sLN + (g2 * 64 + r16 + gq) * 2);
        float2 vb = *(const float2*)(sLN + (g2 * 64 + r16 + gq + 8) * 2);
        sumA += va.x; ssqA += va.y;
        sumB += vb.x; ssqB += vb.y;
    }
    float muA = sumA * (1.0f / DIMD);
    float rsA = rsqrtf(ssqA * (1.0f / DIMD) - muA * muA + EPSV);
    float muB = sumB * (1.0f / DIMD);
    float rsB = rsqrtf(ssqB * (1.0f / DIMD) - muB * muB + EPSV);

    // ================= Phase D: normalize own writes ========================
    for (int c = 0; c < NCH; c++) {
#pragma unroll
        for (int nt = 0; nt < 4; nt++) {
            int col = c * DC + cg * 32 + nt * 8 + 2 * tg;
            float2 g2 = *(const float2*)(gamma + col);
            float2 b2 = *(const float2*)(beta + col);
            float2 ya = *(const float2*)(out + rowA * DIMD + col);
            ya.x = (ya.x - muA) * rsA * g2.x + b2.x;
            ya.y = (ya.y - muA) * rsA * g2.y + b2.y;
            *(float2*)(out + rowA * DIMD + col) = ya;
            float2 yb = *(const float2*)(out + rowB * DIMD + col);
            yb.x = (yb.x - muB) * rsB * g2.x + b2.x;
            yb.y = (yb.y - muB) * rsB * g2.y + b2.y;
            *(float2*)(out + rowB * DIMD + col) = yb;
        }
    }
}

extern "C" void kernel_launch(void* const* d_in, const int* in_sizes, int n_in,
                              void* d_out, int out_size) {
    const float* x     = (const float*)d_in[0];
    const float* Wp    = (const float*)d_in[1];
    const float* bp    = (const float*)d_in[2];
    const float* Wv    = (const float*)d_in[3];
    const float* bv    = (const float*)d_in[4];
    const float* Wi    = (const float*)d_in[5];
    const float* bi    = (const float*)d_in[6];
    const float* gamma = (const float*)d_in[7];
    const float* beta  = (const float*)d_in[8];
    float* out = (float*)d_out;

    wit_kernel<<<(DIMD * NC2) / 256, 256>>>(Wi);
    wt_kernel<<<(32 * DIMD) / 256, 256>>>(Wp, Wv);
    cudaFuncSetAttribute(gil_kernel, cudaFuncAttributeMaxDynamicSharedMemorySize,
                         SMEM_BYTES);
    gil_kernel<<<NCTA, THREADS, SMEM_BYTES>>>(x, Wp, bp, Wv, bv, Wi, bi, gamma,
                                              beta, out);
}

// round 11
// speedup vs baseline: 2.2703x; 1.3163x over previous
#include <cuda_runtime.h>
#include <cstdint>

#define DIMD 2048
#define NC 12
#define NC2 144
#define ROWS 64
#define NCTA 512
#define THREADS 512
#define DC 128
#define NCH 16
#define STRA 144   // Ct stride (words): 144 % 32 == 16 -> LDS.128 conflict-free
#define STRB 144   // B stride (words): exact row, contiguous tile
#define EPSV 1e-5f

// ---- smem byte layout ----
#define OFF_CT 0                       // Ct [64][144] tf32 (36864 B)
#define OFF_B0 36864                   // WiT buf0 [128][144w] (73728 B)
#define OFF_B1 110592                  // WiT buf1 (73728 B)
#define OFF_PV 184320                  // pos/vel [64][24]w (6144 B)
#define OFF_LN 190464                  // LN partials [4][64][2]f (2048 B)
#define OFF_MU 192512                  // mu/rs per row [64]float2 (512 B)
#define SMEM_BYTES 193024
// phase A staging aliases (bytes) inside B0/B1 (dead during phase A)
#define OFF_AX0 36864                  // x fp32 [64][132w] (33792 B)
#define OFF_AX1 70656
#define OFF_AWT0 104448                // Wt tf32 [32][140w] (17920 B)
#define OFF_AWT1 122368                // ends 140288 (inside B1 region: safe)
// phase A reduction alias (word indices; aliases AX bufs, dead by then)
#define FOFF_RED (OFF_B0 / 4)          // partials [8][64][32] (16384 w)
#define FOFF_PV (OFF_PV / 4)

__device__ __align__(16) uint32_t g_WiT[DIMD * NC2];  // [n][perm(k)] tf32
__device__ __align__(16) uint32_t g_WT[32 * DIMD];    // [n][k] tf32 (pos|vel|pad)

__device__ __forceinline__ uint32_t smem_u32(const void* p) {
    uint32_t a;
    asm("{ .reg .u64 t; cvta.to.shared.u64 t, %1; cvt.u32.u64 %0, t; }"
        : "=r"(a) : "l"(p));
    return a;
}
__device__ __forceinline__ uint32_t to_tf32(float x) {
    uint32_t t;
    asm("cvt.rna.tf32.f32 %0, %1;" : "=r"(t) : "f"(x));
    return t;
}
// k16-block permutation: lane tg owns 4 contiguous words = frags for 2 k8 steps
// pos(k) = 16*(k/16) + 4*(k%4) + (k%16)/4
__device__ __forceinline__ int kperm(int k) {
    return (k & ~15) + ((k & 3) << 2) + ((k & 15) >> 2);
}
__device__ __forceinline__ void mma_tf32(float& c0, float& c1, float& c2, float& c3,
                                         uint32_t a0, uint32_t a1, uint32_t a2,
                                         uint32_t a3, uint32_t b0, uint32_t b1) {
    asm volatile(
        "mma.sync.aligned.m16n8k8.row.col.f32.tf32.tf32.f32 "
        "{%0,%1,%2,%3},{%4,%5,%6,%7},{%8,%9},{%0,%1,%2,%3};"
        : "+f"(c0), "+f"(c1), "+f"(c2), "+f"(c3)
        : "r"(a0), "r"(a1), "r"(a2), "r"(a3), "r"(b0), "r"(b1));
}
__device__ __forceinline__ void cpa16(uint32_t dst, const void* src) {
    asm volatile("cp.async.ca.shared.global [%0], [%1], 16;"
                 :: "r"(dst), "l"(src) : "memory");
}

// ---- pre-kernels ----
__global__ void wit_kernel(const float* __restrict__ Wi) {
    int idx = blockIdx.x * 256 + threadIdx.x;  // 144*2048
    int k = idx >> 11;
    int n = idx & 2047;
    g_WiT[n * NC2 + kperm(k)] = to_tf32(Wi[idx]);
}
__global__ void wt_kernel(const float* __restrict__ Wp, const float* __restrict__ Wv) {
    int idx = blockIdx.x * 256 + threadIdx.x;  // 32*2048
    int n = idx >> 11;
    int k = idx & 2047;
    float v = 0.f;
    if (n < NC) v = Wp[k * NC + n];
    else if (n < 2 * NC) v = Wv[k * NC + n - NC];
    g_WT[idx] = to_tf32(v);
}

__global__ __launch_bounds__(THREADS, 1)
void gil_kernel(const float* __restrict__ x, const float* __restrict__ Wp,
                const float* __restrict__ bp, const float* __restrict__ Wv,
                const float* __restrict__ bv, const float* __restrict__ Wi,
                const float* __restrict__ bi, const float* __restrict__ gamma,
                const float* __restrict__ beta, float* __restrict__ out) {
    extern __shared__ char smc[];
    float* smf = (float*)smc;
    uint32_t* smu = (uint32_t*)smc;
    const int tid = threadIdx.x;
    const int w = tid >> 5, lane = tid & 31;
    const int gq = lane >> 2, tg = lane & 3;
    const int rowbase = blockIdx.x * ROWS;
    const uint32_t smem_base = smem_u32(smc);

    // -------- prologue: phase A stage 0 (X + WT, KC=128) --------------------
    {
#pragma unroll
        for (int j = 0; j < 4; j++) {
            int gi = tid + THREADS * j;  // < 2048
            int r = gi >> 5, kq = gi & 31;
            cpa16(smem_base + OFF_AX0 + r * 528 + kq * 16,
                  x + (rowbase + r) * DIMD + kq * 4);
        }
#pragma unroll
        for (int j = 0; j < 2; j++) {
            int gi = tid + THREADS * j;  // < 1024
            int n = gi >> 5, kq = gi & 31;
            cpa16(smem_base + OFF_AWT0 + n * 560 + kq * 16,
                  g_WT + n * DIMD + kq * 4);
        }
        asm volatile("cp.async.commit_group;" ::: "memory");
    }

    // ====== Phase A (tensor): pos/vel = x @ [Wp|Wv], 16 stages of KC=128 ====
    const int k8w = w & 7;   // k16-slice within each 128-k stage
    const int nh = w >> 3;   // n-half
    float pa[8][4];
#pragma unroll
    for (int i = 0; i < 8; i++)
#pragma unroll
        for (int q = 0; q < 4; q++) pa[i][q] = 0.f;

    for (int kc = 0; kc < DIMD / 128; kc++) {
        if (kc < DIMD / 128 - 1) {  // stage kc+1 into alternate buffers
            int kn = kc + 1;
            uint32_t axd = ((kn & 1) ? OFF_AX1 : OFF_AX0);
            uint32_t awd = ((kn & 1) ? OFF_AWT1 : OFF_AWT0);
#pragma unroll
            for (int j = 0; j < 4; j++) {
                int gi = tid + THREADS * j;
                int r = gi >> 5, kq = gi & 31;
                cpa16(smem_base + axd + r * 528 + kq * 16,
                      x + (rowbase + r) * DIMD + kn * 128 + kq * 4);
            }
#pragma unroll
            for (int j = 0; j < 2; j++) {
                int gi = tid + THREADS * j;
                int n = gi >> 5, kq = gi & 31;
                cpa16(smem_base + awd + n * 560 + kq * 16,
                      g_WT + n * DIMD + kn * 128 + kq * 4);
            }
            asm volatile("cp.async.commit_group;" ::: "memory");
            asm volatile("cp.async.wait_group 1;" ::: "memory");
        } else {
            asm volatile("cp.async.wait_group 0;" ::: "memory");
        }
        __syncthreads();  // stage kc copies from ALL threads visible

        const float* X = (const float*)(smc + ((kc & 1) ? OFF_AX1 : OFF_AX0));
        const uint32_t* WT = (const uint32_t*)(smc + ((kc & 1) ? OFF_AWT1 : OFF_AWT0));
        uint32_t wb[2][2][2];  // [k8i][ntile][lo/hi]
#pragma unroll
        for (int k8i = 0; k8i < 2; k8i++) {
            int kb = k8w * 16 + k8i * 8 + tg;
            wb[k8i][0][0] = WT[(nh * 16 + gq) * 140 + kb];
            wb[k8i][0][1] = WT[(nh * 16 + gq) * 140 + kb + 4];
            wb[k8i][1][0] = WT[(nh * 16 + 8 + gq) * 140 + kb];
            wb[k8i][1][1] = WT[(nh * 16 + 8 + gq) * 140 + kb + 4];
        }
#pragma unroll
        for (int m = 0; m < 4; m++) {
#pragma unroll
            for (int k8i = 0; k8i < 2; k8i++) {
                const float* Xr = X + (m * 16 + gq) * 132 + k8w * 16 + k8i * 8 + tg;
                uint32_t a0 = to_tf32(Xr[0]);
                uint32_t a2 = to_tf32(Xr[4]);
                uint32_t a1 = to_tf32(Xr[8 * 132]);
                uint32_t a3 = to_tf32(Xr[8 * 132 + 4]);
                mma_tf32(pa[2 * m][0], pa[2 * m][1], pa[2 * m][2], pa[2 * m][3],
                         a0, a1, a2, a3, wb[k8i][0][0], wb[k8i][0][1]);
                mma_tf32(pa[2 * m + 1][0], pa[2 * m + 1][1], pa[2 * m + 1][2],
                         pa[2 * m + 1][3], a0, a1, a2, a3,
                         wb[k8i][1][0], wb[k8i][1][1]);
            }
        }
        __syncthreads();  // all warps done with this stage buffer
    }
    // write per-slice partials (RED aliases AX staging; consumption done)
#pragma unroll
    for (int m = 0; m < 4; m++) {
#pragma unroll
        for (int j = 0; j < 2; j++) {
            int n = (2 * nh + j) * 8 + 2 * tg;
            float* dst = smf + FOFF_RED + k8w * 2048 + (m * 16 + gq) * 32 + n;
            *(float2*)dst = make_float2(pa[2 * m + j][0], pa[2 * m + j][1]);
            *(float2*)(dst + 8 * 32) = make_float2(pa[2 * m + j][2], pa[2 * m + j][3]);
        }
    }
    __syncthreads();
    // reduce 8 k-slices + bias -> sPV (dedicated region)
#pragma unroll
    for (int q = 0; q < 3; q++) {
        int o = tid + THREADS * q;  // < 1536
        int row = o / 24, c = o - row * 24;
        float v = 0.f;
#pragma unroll
        for (int s = 0; s < 8; s++) v += smf[FOFF_RED + s * 2048 + row * 32 + c];
        v += (c < NC) ? bp[c] : bv[c - NC];
        smf[FOFF_PV + row * 24 + c] = v;
    }
    __syncthreads();  // PV ready; RED/staging (B0/B1 region) now dead

    // -------- issue Wi chunk-0 prefetch (contiguous; hides behind phase B) --
    {
        const char* src = (const char*)g_WiT;
#pragma unroll
        for (int j = 0; j < 9; j++) {
            int e = (tid + THREADS * j) * 16;  // < 73728
            cpa16(smem_base + OFF_B0 + e, src + e);
        }
        asm volatile("cp.async.commit_group;" ::: "memory");
    }

    // ============ Phase B: sCt[row][perm(k)] ================================
#pragma unroll
    for (int q = 0; q < 18; q++) {
        int t = tid + THREADS * q;  // < 9216
        int row = t / NC2;
        int k = t - row * NC2;
        int i = k / NC, j = k - i * NC;
        float ct = smf[FOFF_PV + row * 24 + i] * smf[FOFF_PV + row * 24 + NC + j];
        smu[row * STRA + kperm(k)] = to_tf32(ct);
    }
    __syncthreads();  // Ct visible to all warps

    // ===== Hoist A-fragments (LDS.128; reused across all chunks) ============
    const int r16 = (w & 3) * 16;
    const int cg = w >> 2;
    const int rowA = rowbase + r16 + gq;
    const int rowB = rowA + 8;
    uint4 afA[9], afB[9];  // afA: rows gq (a0,a2) x 2 k8 ; afB: rows gq+8 (a1,a3)
    {
        const uint32_t* A0 = smu + (r16 + gq) * STRA + 4 * tg;
        const uint32_t* A1 = A0 + 8 * STRA;
#pragma unroll
        for (int k16 = 0; k16 < 9; k16++) {
            afA[k16] = *(const uint4*)(A0 + k16 * 16);
            afB[k16] = *(const uint4*)(A1 + k16 * 16);
        }
    }

    // ================= Phase C: chunk loop ==================================
    float lsA = 0.f, qA = 0.f, lsB = 0.f, qB = 0.f;

    for (int c = 0; c < NCH; c++) {
        if (c < NCH - 1) {
            const char* src = (const char*)g_WiT + (c + 1) * DC * NC2 * 4;
            uint32_t bufoff = ((c + 1) & 1) ? OFF_B1 : OFF_B0;
#pragma unroll
            for (int j = 0; j < 9; j++) {
                int e = (tid + THREADS * j) * 16;
                cpa16(smem_base + bufoff + e, src + e);
            }
            asm volatile("cp.async.commit_group;" ::: "memory");
            asm volatile("cp.async.wait_group 1;" ::: "memory");
        } else {
            asm volatile("cp.async.wait_group 0;" ::: "memory");
        }
        __syncthreads();  // chunk c copies from ALL threads visible

        // prefetch this chunk's x rows into registers (hidden by MMA loop)
        int cbase = c * DC + cg * 32;
        float2 xpa[4], xpb[4];
#pragma unroll
        for (int nt = 0; nt < 4; nt++) {
            int col = cbase + nt * 8 + 2 * tg;
            xpa[nt] = *(const float2*)(x + rowA * DIMD + col);
            xpb[nt] = *(const float2*)(x + rowB * DIMD + col);
        }

        const uint32_t* Bb = smu + ((c & 1) ? OFF_B1 : OFF_B0) / 4 +
                             (cg * 32 + gq) * STRB + 4 * tg;
        float acc[4][4];
#pragma unroll
        for (int nt = 0; nt < 4; nt++)
#pragma unroll
            for (int q = 0; q < 4; q++) acc[nt][q] = 0.f;

#pragma unroll
        for (int k16 = 0; k16 < 9; k16++) {
            uint4 b0 = *(const uint4*)(Bb + 0 * 8 * STRB + k16 * 16);
            uint4 b1 = *(const uint4*)(Bb + 1 * 8 * STRB + k16 * 16);
            uint4 b2 = *(const uint4*)(Bb + 2 * 8 * STRB + k16 * 16);
            uint4 b3 = *(const uint4*)(Bb + 3 * 8 * STRB + k16 * 16);
            // k8a: (afA.x,.y) rows, B words .x,.y
            mma_tf32(acc[0][0], acc[0][1], acc[0][2], acc[0][3],
                     afA[k16].x, afB[k16].x, afA[k16].y, afB[k16].y, b0.x, b0.y);
            mma_tf32(acc[1][0], acc[1][1], acc[1][2], acc[1][3],
                     afA[k16].x, afB[k16].x, afA[k16].y, afB[k16].y, b1.x, b1.y);
            mma_tf32(acc[2][0], acc[2][1], acc[2][2], acc[2][3],
                     afA[k16].x, afB[k16].x, afA[k16].y, afB[k16].y, b2.x, b2.y);
            mma_tf32(acc[3][0], acc[3][1], acc[3][2], acc[3][3],
                     afA[k16].x, afB[k16].x, afA[k16].y, afB[k16].y, b3.x, b3.y);
            // k8b: (afA.z,.w) rows, B words .z,.w
            mma_tf32(acc[0][0], acc[0][1], acc[0][2], acc[0][3],
                     afA[k16].z, afB[k16].z, afA[k16].w, afB[k16].w, b0.z, b0.w);
            mma_tf32(acc[1][0], acc[1][1], acc[1][2], acc[1][3],
                     afA[k16].z, afB[k16].z, afA[k16].w, afB[k16].w, b1.z, b1.w);
            mma_tf32(acc[2][0], acc[2][1], acc[2][2], acc[2][3],
                     afA[k16].z, afB[k16].z, afA[k16].w, afB[k16].w, b2.z, b2.w);
            mma_tf32(acc[3][0], acc[3][1], acc[3][2], acc[3][3],
                     afA[k16].z, afB[k16].z, afA[k16].w, afB[k16].w, b3.z, b3.w);
        }

        // epilogue: y = inter + x + bi ; store ; LN partials
#pragma unroll
        for (int nt = 0; nt < 4; nt++) {
            int col = cbase + nt * 8 + 2 * tg;
            float2 biv = *(const float2*)(bi + col);
            float y0 = acc[nt][0] + xpa[nt].x + biv.x;
            float y1 = acc[nt][1] + xpa[nt].y + biv.y;
            *(float2*)(out + rowA * DIMD + col) = make_float2(y0, y1);
            lsA += y0 + y1;
            qA += y0 * y0 + y1 * y1;
            float y2 = acc[nt][2] + xpb[nt].x + biv.x;
            float y3 = acc[nt][3] + xpb[nt].y + biv.y;
            *(float2*)(out + rowB * DIMD + col) = make_float2(y2, y3);
            lsB += y2 + y3;
            qB += y2 * y2 + y3 * y3;
        }
        __syncthreads();  // done reading buf[c&1] before next prefetch
    }

    // ================= LN stats =============================================
#pragma unroll
    for (int off = 1; off <= 2; off <<= 1) {
        lsA += __shfl_xor_sync(0xffffffffu, lsA, off);
        qA += __shfl_xor_sync(0xffffffffu, qA, off);
        lsB += __shfl_xor_sync(0xffffffffu, lsB, off);
        qB += __shfl_xor_sync(0xffffffffu, qB, off);
    }
    float* sLN = (float*)(smc + OFF_LN);
    if (tg == 0) {
        int rA = r16 + gq, rB = rA + 8;
        *(float2*)(sLN + (cg * 64 + rA) * 2) = make_float2(lsA, qA);
        *(float2*)(sLN + (cg * 64 + rB) * 2) = make_float2(lsB, qB);
    }
    __syncthreads();
    // per-row mu/rs -> sMuRs
    float2* sMuRs = (float2*)(smc + OFF_MU);
    if (tid < ROWS) {
        float s = 0.f, q = 0.f;
#pragma unroll
        for (int g2 = 0; g2 < 4; g2++) {
            float2 v = *(const float2*)(sLN + (g2 * 64 + tid) * 2);
            s += v.x;
            q += v.y;
        }
        float mu = s * (1.0f / DIMD);
        float rs = rsqrtf(q * (1.0f / DIMD) - mu * mu + EPSV);
        sMuRs[tid] = make_float2(mu, rs);
    }
    __syncthreads();  // also orders phase C global writes for cross-warp read

    // ===== Phase D: warp w owns rows 4w..4w+3, full width, float4 ===========
    float2 mr[4];
#pragma unroll
    for (int r = 0; r < 4; r++) mr[r] = sMuRs[4 * w + r];
#pragma unroll
    for (int it = 0; it < 16; it++) {
        int col = it * 128 + lane * 4;
        float4 g4 = *(const float4*)(gamma + col);
        float4 b4 = *(const float4*)(beta + col);
#pragma unroll
        for (int r = 0; r < 4; r++) {
            int row = rowbase + 4 * w + r;
            float4 yv = *(const float4*)(out + row * DIMD + col);
            float4 o;
            o.x = (yv.x - mr[r].x) * mr[r].y * g4.x + b4.x;
            o.y = (yv.y - mr[r].x) * mr[r].y * g4.y + b4.y;
            o.z = (yv.z - mr[r].x) * mr[r].y * g4.z + b4.z;
            o.w = (yv.w - mr[r].x) * mr[r].y * g4.w + b4.w;
            *(float4*)(out + row * DIMD + col) = o;
        }
    }
}

extern "C" void kernel_launch(void* const* d_in, const int* in_sizes, int n_in,
                              void* d_out, int out_size) {
    const float* x     = (const float*)d_in[0];
    const float* Wp    = (const float*)d_in[1];
    const float* bp    = (const float*)d_in[2];
    const float* Wv    = (const float*)d_in[3];
    const float* bv    = (const float*)d_in[4];
    const float* Wi    = (const float*)d_in[5];
    const float* bi    = (const float*)d_in[6];
    const float* gamma = (const float*)d_in[7];
    const float* beta  = (const float*)d_in[8];
    float* out = (float*)d_out;

    wit_kernel<<<(DIMD * NC2) / 256, 256>>>(Wi);
    wt_kernel<<<(32 * DIMD) / 256, 256>>>(Wp, Wv);
    cudaFuncSetAttribute(gil_kernel, cudaFuncAttributeMaxDynamicSharedMemorySize,
                         SMEM_BYTES);
    gil_kernel<<<NCTA, THREADS, SMEM_BYTES>>>(x, Wp, bp, Wv, bv, Wi, bi, gamma,
                                              beta, out);
}

// round 12
// speedup vs baseline: 2.3156x; 1.0200x over previous
#include <cuda_runtime.h>
#include <cstdint>

#define DIMD 2048
#define NC 12
#define NC2 144
#define ROWS 64
#define NCTA 512
#define THREADS 512
#define DC 128
#define NCH 16
#define STRA 144   // Ct stride (words): 144 % 32 == 16 -> LDS.128 conflict-free
#define STRB 144   // B stride (words): exact row, contiguous tile
#define EPSV 1e-5f

// ---- smem byte layout ----
#define OFF_CT 0                       // Ct [64][144] tf32 (36864 B)
#define OFF_B0 36864                   // WiT buf0 [128][144w] (73728 B)
#define OFF_B1 110592                  // WiT buf1 (73728 B)
#define OFF_PV 184320                  // pos/vel [64][24]w (6144 B)
#define OFF_LN 190464                  // LN partials [4][64][2]f (2048 B)
#define SMEM_BYTES 192512
// phase A staging aliases (bytes) inside B0/B1 (dead during phase A)
#define OFF_AX0 36864                  // x fp32 [64][132w] (33792 B)
#define OFF_AX1 70656
#define OFF_AWT0 104448                // Wt tf32 [32][140w] (17920 B)
#define OFF_AWT1 122368                // ends 140288 (inside B1 region: safe)
// phase A reduction alias (word indices; aliases AX bufs, dead by then)
#define FOFF_RED (OFF_B0 / 4)          // partials [8][64][32] (16384 w)
#define FOFF_PV (OFF_PV / 4)

__device__ __align__(16) uint32_t g_WiT[DIMD * NC2];  // [pos][perm(k)] tf32
__device__ __align__(16) uint32_t g_WT[32 * DIMD];    // [n][k] tf32 (pos|vel|pad)
__device__ __align__(16) float2 g_MuRs[32768];        // per-row (mu, rsqrt)

__device__ __forceinline__ uint32_t smem_u32(const void* p) {
    uint32_t a;
    asm("{ .reg .u64 t; cvta.to.shared.u64 t, %1; cvt.u32.u64 %0, t; }"
        : "=r"(a) : "l"(p));
    return a;
}
__device__ __forceinline__ uint32_t to_tf32(float x) {
    uint32_t t;
    asm("cvt.rna.tf32.f32 %0, %1;" : "=r"(t) : "f"(x));
    return t;
}
// k16-block permutation: lane tg owns 4 contiguous words = frags for 2 k8 steps
__device__ __forceinline__ int kperm(int k) {
    return (k & ~15) + ((k & 3) << 2) + ((k & 15) >> 2);
}
// n-permutation within each 32-col group: tile-pos p -> global col offset
// (so each thread's epilogue columns are two contiguous float4s)
__device__ __forceinline__ int nperm(int p) {
    int nt = p >> 3, tg = (p >> 1) & 3, j = p & 1;
    return ((nt >> 1) << 4) + ((nt & 1) << 1) + (tg << 2) + j;
}
__device__ __forceinline__ void mma_tf32(float& c0, float& c1, float& c2, float& c3,
                                         uint32_t a0, uint32_t a1, uint32_t a2,
                                         uint32_t a3, uint32_t b0, uint32_t b1) {
    asm volatile(
        "mma.sync.aligned.m16n8k8.row.col.f32.tf32.tf32.f32 "
        "{%0,%1,%2,%3},{%4,%5,%6,%7},{%8,%9},{%0,%1,%2,%3};"
        : "+f"(c0), "+f"(c1), "+f"(c2), "+f"(c3)
        : "r"(a0), "r"(a1), "r"(a2), "r"(a3), "r"(b0), "r"(b1));
}
__device__ __forceinline__ void cpa16(uint32_t dst, const void* src) {
    asm volatile("cp.async.ca.shared.global [%0], [%1], 16;"
                 :: "r"(dst), "l"(src) : "memory");
}

// ---- pre-kernels ----
__global__ void wit_kernel(const float* __restrict__ Wi) {
    int idx = blockIdx.x * 256 + threadIdx.x;  // 144*2048
    int k = idx >> 11;
    int pos = idx & 2047;
    int nsrc = (pos & ~31) + nperm(pos & 31);
    g_WiT[pos * NC2 + kperm(k)] = to_tf32(Wi[k * DIMD + nsrc]);
}
__global__ void wt_kernel(const float* __restrict__ Wp, const float* __restrict__ Wv) {
    int idx = blockIdx.x * 256 + threadIdx.x;  // 32*2048
    int n = idx >> 11;
    int k = idx & 2047;
    float v = 0.f;
    if (n < NC) v = Wp[k * NC + n];
    else if (n < 2 * NC) v = Wv[k * NC + n - NC];
    g_WT[idx] = to_tf32(v);
}

// ---- post-kernel: high-occupancy LayerNorm apply ----
__global__ __launch_bounds__(256, 8)
void ln_kernel(const float* __restrict__ gamma, const float* __restrict__ beta,
               float* __restrict__ out) {
    int warp = threadIdx.x >> 5, lane = threadIdx.x & 31;
    int row = blockIdx.x * 8 + warp;
    float2 mr = g_MuRs[row];
    float* rp = out + row * DIMD;
#pragma unroll
    for (int it = 0; it < 16; it++) {
        int col = it * 128 + lane * 4;
        float4 g4 = *(const float4*)(gamma + col);
        float4 b4 = *(const float4*)(beta + col);
        float4 yv = *(const float4*)(rp + col);
        float4 o;
        o.x = (yv.x - mr.x) * mr.y * g4.x + b4.x;
        o.y = (yv.y - mr.x) * mr.y * g4.y + b4.y;
        o.z = (yv.z - mr.x) * mr.y * g4.z + b4.z;
        o.w = (yv.w - mr.x) * mr.y * g4.w + b4.w;
        *(float4*)(rp + col) = o;
    }
}

__global__ __launch_bounds__(THREADS, 1)
void gil_kernel(const float* __restrict__ x, const float* __restrict__ Wp,
                const float* __restrict__ bp, const float* __restrict__ Wv,
                const float* __restrict__ bv, const float* __restrict__ Wi,
                const float* __restrict__ bi, const float* __restrict__ gamma,
                const float* __restrict__ beta, float* __restrict__ out) {
    extern __shared__ char smc[];
    float* smf = (float*)smc;
    uint32_t* smu = (uint32_t*)smc;
    const int tid = threadIdx.x;
    const int w = tid >> 5, lane = tid & 31;
    const int gq = lane >> 2, tg = lane & 3;
    const int rowbase = blockIdx.x * ROWS;
    const uint32_t smem_base = smem_u32(smc);

    // -------- prologue: phase A stage 0 (X + WT, KC=128) --------------------
    {
#pragma unroll
        for (int j = 0; j < 4; j++) {
            int gi = tid + THREADS * j;  // < 2048
            int r = gi >> 5, kq = gi & 31;
            cpa16(smem_base + OFF_AX0 + r * 528 + kq * 16,
                  x + (rowbase + r) * DIMD + kq * 4);
        }
#pragma unroll
        for (int j = 0; j < 2; j++) {
            int gi = tid + THREADS * j;  // < 1024
            int n = gi >> 5, kq = gi & 31;
            cpa16(smem_base + OFF_AWT0 + n * 560 + kq * 16,
                  g_WT + n * DIMD + kq * 4);
        }
        asm volatile("cp.async.commit_group;" ::: "memory");
    }

    // ====== Phase A (tensor): pos/vel = x @ [Wp|Wv], 16 stages of KC=128 ====
    const int k8w = w & 7;   // k16-slice within each 128-k stage
    const int nh = w >> 3;   // n-half
    float pa[8][4];
#pragma unroll
    for (int i = 0; i < 8; i++)
#pragma unroll
        for (int q = 0; q < 4; q++) pa[i][q] = 0.f;

    for (int kc = 0; kc < DIMD / 128; kc++) {
        if (kc < DIMD / 128 - 1) {  // stage kc+1 into alternate buffers
            int kn = kc + 1;
            uint32_t axd = ((kn & 1) ? OFF_AX1 : OFF_AX0);
            uint32_t awd = ((kn & 1) ? OFF_AWT1 : OFF_AWT0);
#pragma unroll
            for (int j = 0; j < 4; j++) {
                int gi = tid + THREADS * j;
                int r = gi >> 5, kq = gi & 31;
                cpa16(smem_base + axd + r * 528 + kq * 16,
                      x + (rowbase + r) * DIMD + kn * 128 + kq * 4);
            }
#pragma unroll
            for (int j = 0; j < 2; j++) {
                int gi = tid + THREADS * j;
                int n = gi >> 5, kq = gi & 31;
                cpa16(smem_base + awd + n * 560 + kq * 16,
                      g_WT + n * DIMD + kn * 128 + kq * 4);
            }
            asm volatile("cp.async.commit_group;" ::: "memory");
            asm volatile("cp.async.wait_group 1;" ::: "memory");
        } else {
            asm volatile("cp.async.wait_group 0;" ::: "memory");
        }
        __syncthreads();  // stage kc copies from ALL threads visible

        const float* X = (const float*)(smc + ((kc & 1) ? OFF_AX1 : OFF_AX0));
        const uint32_t* WT = (const uint32_t*)(smc + ((kc & 1) ? OFF_AWT1 : OFF_AWT0));
        uint32_t wb[2][2][2];  // [k8i][ntile][lo/hi]
#pragma unroll
        for (int k8i = 0; k8i < 2; k8i++) {
            int kb = k8w * 16 + k8i * 8 + tg;
            wb[k8i][0][0] = WT[(nh * 16 + gq) * 140 + kb];
            wb[k8i][0][1] = WT[(nh * 16 + gq) * 140 + kb + 4];
            wb[k8i][1][0] = WT[(nh * 16 + 8 + gq) * 140 + kb];
            wb[k8i][1][1] = WT[(nh * 16 + 8 + gq) * 140 + kb + 4];
        }
#pragma unroll
        for (int m = 0; m < 4; m++) {
#pragma unroll
            for (int k8i = 0; k8i < 2; k8i++) {
                const float* Xr = X + (m * 16 + gq) * 132 + k8w * 16 + k8i * 8 + tg;
                uint32_t a0 = to_tf32(Xr[0]);
                uint32_t a2 = to_tf32(Xr[4]);
                uint32_t a1 = to_tf32(Xr[8 * 132]);
                uint32_t a3 = to_tf32(Xr[8 * 132 + 4]);
                mma_tf32(pa[2 * m][0], pa[2 * m][1], pa[2 * m][2], pa[2 * m][3],
                         a0, a1, a2, a3, wb[k8i][0][0], wb[k8i][0][1]);
                mma_tf32(pa[2 * m + 1][0], pa[2 * m + 1][1], pa[2 * m + 1][2],
                         pa[2 * m + 1][3], a0, a1, a2, a3,
                         wb[k8i][1][0], wb[k8i][1][1]);
            }
        }
        __syncthreads();  // all warps done with this stage buffer
    }
    // write per-slice partials (RED aliases AX staging; consumption done)
#pragma unroll
    for (int m = 0; m < 4; m++) {
#pragma unroll
        for (int j = 0; j < 2; j++) {
            int n = (2 * nh + j) * 8 + 2 * tg;
            float* dst = smf + FOFF_RED + k8w * 2048 + (m * 16 + gq) * 32 + n;
            *(float2*)dst = make_float2(pa[2 * m + j][0], pa[2 * m + j][1]);
            *(float2*)(dst + 8 * 32) = make_float2(pa[2 * m + j][2], pa[2 * m + j][3]);
        }
    }
    __syncthreads();
    // reduce 8 k-slices + bias -> sPV (dedicated region)
#pragma unroll
    for (int q = 0; q < 3; q++) {
        int o = tid + THREADS * q;  // < 1536
        int row = o / 24, c = o - row * 24;
        float v = 0.f;
#pragma unroll
        for (int s = 0; s < 8; s++) v += smf[FOFF_RED + s * 2048 + row * 32 + c];
        v += (c < NC) ? bp[c] : bv[c - NC];
        smf[FOFF_PV + row * 24 + c] = v;
    }
    __syncthreads();  // PV ready; RED/staging (B0/B1 region) now dead

    // -------- issue Wi chunk-0 prefetch (contiguous; hides behind phase B) --
    {
        const char* src = (const char*)g_WiT;
#pragma unroll
        for (int j = 0; j < 9; j++) {
            int e = (tid + THREADS * j) * 16;  // < 73728
            cpa16(smem_base + OFF_B0 + e, src + e);
        }
        asm volatile("cp.async.commit_group;" ::: "memory");
    }

    // ============ Phase B: sCt[row][perm(k)] ================================
#pragma unroll
    for (int q = 0; q < 18; q++) {
        int t = tid + THREADS * q;  // < 9216
        int row = t / NC2;
        int k = t - row * NC2;
        int i = k / NC, j = k - i * NC;
        float ct = smf[FOFF_PV + row * 24 + i] * smf[FOFF_PV + row * 24 + NC + j];
        smu[row * STRA + kperm(k)] = to_tf32(ct);
    }
    __syncthreads();  // Ct visible to all warps

    // ===== Hoist A-fragments (LDS.128; reused across all chunks) ============
    const int r16 = (w & 3) * 16;
    const int cg = w >> 2;
    const int rowA = rowbase + r16 + gq;
    const int rowB = rowA + 8;
    uint4 afA[9], afB[9];
    {
        const uint32_t* A0 = smu + (r16 + gq) * STRA + 4 * tg;
        const uint32_t* A1 = A0 + 8 * STRA;
#pragma unroll
        for (int k16 = 0; k16 < 9; k16++) {
            afA[k16] = *(const uint4*)(A0 + k16 * 16);
            afB[k16] = *(const uint4*)(A1 + k16 * 16);
        }
    }

    // ================= Phase C: chunk loop ==================================
    float lsA = 0.f, qA = 0.f, lsB = 0.f, qB = 0.f;

    for (int c = 0; c < NCH; c++) {
        if (c < NCH - 1) {
            const char* src = (const char*)g_WiT + (c + 1) * DC * NC2 * 4;
            uint32_t bufoff = ((c + 1) & 1) ? OFF_B1 : OFF_B0;
#pragma unroll
            for (int j = 0; j < 9; j++) {
                int e = (tid + THREADS * j) * 16;
                cpa16(smem_base + bufoff + e, src + e);
            }
            asm volatile("cp.async.commit_group;" ::: "memory");
            asm volatile("cp.async.wait_group 1;" ::: "memory");
        } else {
            asm volatile("cp.async.wait_group 0;" ::: "memory");
        }
        __syncthreads();  // chunk c copies from ALL threads visible

        // this thread's two contiguous float4 column groups (via n-perm)
        int cbase = c * DC + cg * 32;
        int col0 = cbase + 4 * tg;
        int col1 = col0 + 16;
        // prefetch x rows into registers (hidden by MMA loop)
        float4 xa0 = *(const float4*)(x + rowA * DIMD + col0);
        float4 xa1 = *(const float4*)(x + rowA * DIMD + col1);
        float4 xb0 = *(const float4*)(x + rowB * DIMD + col0);
        float4 xb1 = *(const float4*)(x + rowB * DIMD + col1);

        const uint32_t* Bb = smu + ((c & 1) ? OFF_B1 : OFF_B0) / 4 +
                             (cg * 32 + gq) * STRB + 4 * tg;
        float acc[4][4];
#pragma unroll
        for (int nt = 0; nt < 4; nt++)
#pragma unroll
            for (int q = 0; q < 4; q++) acc[nt][q] = 0.f;

#pragma unroll
        for (int k16 = 0; k16 < 9; k16++) {
            uint4 b0 = *(const uint4*)(Bb + 0 * 8 * STRB + k16 * 16);
            uint4 b1 = *(const uint4*)(Bb + 1 * 8 * STRB + k16 * 16);
            uint4 b2 = *(const uint4*)(Bb + 2 * 8 * STRB + k16 * 16);
            uint4 b3 = *(const uint4*)(Bb + 3 * 8 * STRB + k16 * 16);
            mma_tf32(acc[0][0], acc[0][1], acc[0][2], acc[0][3],
                     afA[k16].x, afB[k16].x, afA[k16].y, afB[k16].y, b0.x, b0.y);
            mma_tf32(acc[1][0], acc[1][1], acc[1][2], acc[1][3],
                     afA[k16].x, afB[k16].x, afA[k16].y, afB[k16].y, b1.x, b1.y);
            mma_tf32(acc[2][0], acc[2][1], acc[2][2], acc[2][3],
                     afA[k16].x, afB[k16].x, afA[k16].y, afB[k16].y, b2.x, b2.y);
            mma_tf32(acc[3][0], acc[3][1], acc[3][2], acc[3][3],
                     afA[k16].x, afB[k16].x, afA[k16].y, afB[k16].y, b3.x, b3.y);
            mma_tf32(acc[0][0], acc[0][1], acc[0][2], acc[0][3],
                     afA[k16].z, afB[k16].z, afA[k16].w, afB[k16].w, b0.z, b0.w);
            mma_tf32(acc[1][0], acc[1][1], acc[1][2], acc[1][3],
                     afA[k16].z, afB[k16].z, afA[k16].w, afB[k16].w, b1.z, b1.w);
            mma_tf32(acc[2][0], acc[2][1], acc[2][2], acc[2][3],
                     afA[k16].z, afB[k16].z, afA[k16].w, afB[k16].w, b2.z, b2.w);
            mma_tf32(acc[3][0], acc[3][1], acc[3][2], acc[3][3],
                     afA[k16].z, afB[k16].z, afA[k16].w, afB[k16].w, b3.z, b3.w);
        }

        // epilogue: y = inter + x + bi ; float4 stores ; LN partials
        // col0 group: acc tiles 0,1 ; col1 group: acc tiles 2,3
        float4 bi0 = *(const float4*)(bi + col0);
        float4 bi1 = *(const float4*)(bi + col1);
        float4 ya0, ya1, yb0, yb1;
        ya0.x = acc[0][0] + xa0.x + bi0.x;
        ya0.y = acc[0][1] + xa0.y + bi0.y;
        ya0.z = acc[1][0] + xa0.z + bi0.z;
        ya0.w = acc[1][1] + xa0.w + bi0.w;
        ya1.x = acc[2][0] + xa1.x + bi1.x;
        ya1.y = acc[2][1] + xa1.y + bi1.y;
        ya1.z = acc[3][0] + xa1.z + bi1.z;
        ya1.w = acc[3][1] + xa1.w + bi1.w;
        yb0.x = acc[0][2] + xb0.x + bi0.x;
        yb0.y = acc[0][3] + xb0.y + bi0.y;
        yb0.z = acc[1][2] + xb0.z + bi0.z;
        yb0.w = acc[1][3] + xb0.w + bi0.w;
        yb1.x = acc[2][2] + xb1.x + bi1.x;
        yb1.y = acc[2][3] + xb1.y + bi1.y;
        yb1.z = acc[3][2] + xb1.z + bi1.z;
        yb1.w = acc[3][3] + xb1.w + bi1.w;
        *(float4*)(out + rowA * DIMD + col0) = ya0;
        *(float4*)(out + rowA * DIMD + col1) = ya1;
        *(float4*)(out + rowB * DIMD + col0) = yb0;
        *(float4*)(out + rowB * DIMD + col1) = yb1;
        lsA += (ya0.x + ya0.y + ya0.z + ya0.w) + (ya1.x + ya1.y + ya1.z + ya1.w);
        qA += ya0.x * ya0.x + ya0.y * ya0.y + ya0.z * ya0.z + ya0.w * ya0.w +
              ya1.x * ya1.x + ya1.y * ya1.y + ya1.z * ya1.z + ya1.w * ya1.w;
        lsB += (yb0.x + yb0.y + yb0.z + yb0.w) + (yb1.x + yb1.y + yb1.z + yb1.w);
        qB += yb0.x * yb0.x + yb0.y * yb0.y + yb0.z * yb0.z + yb0.w * yb0.w +
              yb1.x * yb1.x + yb1.y * yb1.y + yb1.z * yb1.z + yb1.w * yb1.w;
        __syncthreads();  // done reading buf[c&1] before next prefetch
    }

    // ================= LN stats -> g_MuRs ===================================
#pragma unroll
    for (int off = 1; off <= 2; off <<= 1) {
        lsA += __shfl_xor_sync(0xffffffffu, lsA, off);
        qA += __shfl_xor_sync(0xffffffffu, qA, off);
        lsB += __shfl_xor_sync(0xffffffffu, lsB, off);
        qB += __shfl_xor_sync(0xffffffffu, qB, off);
    }
    float* sLN = (float*)(smc + OFF_LN);
    if (tg == 0) {
        int rA = r16 + gq, rB = rA + 8;
        *(float2*)(sLN + (cg * 64 + rA) * 2) = make_float2(lsA, qA);
        *(float2*)(sLN + (cg * 64 + rB) * 2) = make_float2(lsB, qB);
    }
    __syncthreads();
    if (tid < ROWS) {
        float s = 0.f, q = 0.f;
#pragma unroll
        for (int g2 = 0; g2 < 4; g2++) {
            float2 v = *(const float2*)(sLN + (g2 * 64 + tid) * 2);
            s += v.x;
            q += v.y;
        }
        float mu = s * (1.0f / DIMD);
        float rs = rsqrtf(q * (1.0f / DIMD) - mu * mu + EPSV);
        g_MuRs[rowbase + tid] = make_float2(mu, rs);
    }
}

extern "C" void kernel_launch(void* const* d_in, const int* in_sizes, int n_in,
                              void* d_out, int out_size) {
    const float* x     = (const float*)d_in[0];
    const float* Wp    = (const float*)d_in[1];
    const float* bp    = (const float*)d_in[2];
    const float* Wv    = (const float*)d_in[3];
    const float* bv    = (const float*)d_in[4];
    const float* Wi    = (const float*)d_in[5];
    const float* bi    = (const float*)d_in[6];
    const float* gamma = (const float*)d_in[7];
    const float* beta  = (const float*)d_in[8];
    float* out = (float*)d_out;

    wit_kernel<<<(DIMD * NC2) / 256, 256>>>(Wi);
    wt_kernel<<<(32 * DIMD) / 256, 256>>>(Wp, Wv);
    cudaFuncSetAttribute(gil_kernel, cudaFuncAttributeMaxDynamicSharedMemorySize,
                         SMEM_BYTES);
    gil_kernel<<<NCTA, THREADS, SMEM_BYTES>>>(x, Wp, bp, Wv, bv, Wi, bi, gamma,
                                              beta, out);
    ln_kernel<<<32768 / 8, 256>>>(gamma, beta, out);
}